// round 6
// baseline (speedup 1.0000x reference)
#include <cuda_runtime.h>

#define NB 8
#define CI 256
#define TL 1024
#define EMB 512
#define OC 256
#define NH 8
#define DH 64
#define DVH 32

// Scratch (device globals — no allocation allowed)
// All四 tensors are stored tf32-pre-rounded by their producers (consumers used
// to round at load anyway -> bit-identical results, fewer CVTs).
__device__ float g_Q[NB*NH*TL*DH];   // (n,h,t,64), pre-scaled by 0.125
__device__ float g_K[NB*NH*TL*DH];   // (n,h,t,64)
__device__ float g_V[NB*NH*TL*DVH];  // (n,h,t,32)
__device__ float g_A[NB*OC*TL];      // attention output, (n,c,t)

// ---------------------------------------------------------------------------
__device__ __forceinline__ float f2tf(float f) {
    unsigned u;
    asm("cvt.rna.tf32.f32 %0, %1;" : "=r"(u) : "f"(f));
    return __uint_as_float(u);
}

__device__ __forceinline__ void mma_tf32(float c[4], const unsigned a[4], const unsigned b[2]) {
    asm volatile(
        "mma.sync.aligned.m16n8k8.row.col.f32.tf32.tf32.f32 "
        "{%0,%1,%2,%3}, {%4,%5,%6,%7}, {%8,%9}, {%0,%1,%2,%3};"
        : "+f"(c[0]), "+f"(c[1]), "+f"(c[2]), "+f"(c[3])
        : "r"(a[0]), "r"(a[1]), "r"(a[2]), "r"(a[3]),
          "r"(b[0]), "r"(b[1]));
}

// ---------------------------------------------------------------------------
// Projection GEMM smem layout (fragment-packed, double-buffered):
//   Apack[buf]: 8 blocks (m>>4) x 4 kt x 32 lanes x float4  -> 4096 floats/buf
//   Bpack[buf]: (2 wn x 4 kt x 8 j) x 32 lanes x float2     -> 4096 floats/buf
// Epilogue staging (128 x 132) overlays the buffers after the mainloop.
#define APK(buf) ((buf)*4096)
#define BPK(buf) (8192 + (buf)*4096)
#define PROJ_SMEM_FLOATS 16896

// ---------------------------------------------------------------------------
// QKV projection: CTA 128(M) x 128(N), warp tile 32x64, K-chunks of 32.
// ---------------------------------------------------------------------------
__global__ __launch_bounds__(256) void qkv_mma(
    const float* __restrict__ x,
    const float* __restrict__ Wq,  const float* __restrict__ bq,
    const float* __restrict__ Wkv, const float* __restrict__ bkv)
{
    extern __shared__ float sm[];
    const int n  = blockIdx.z;
    const int m0 = blockIdx.y * 128;
    const int t0 = blockIdx.x * 128;
    const int tid = threadIdx.x;
    const int wid = tid >> 5, lane = tid & 31;
    const int wm = wid & 3, wn = wid >> 2;
    const float* xb = x + (size_t)n * CI * TL;
    // m0 is 128-aligned -> whole CTA reads one weight matrix
    const float* Wbase = (m0 < EMB) ? (Wq + (size_t)m0*CI) : (Wkv + (size_t)(m0-EMB)*CI);

    float C[2][8][4] = {};

    auto load_chunk = [&](int k0, int buf) {
        // A: W rows m0..m0+127, k-cols k0..k0+31  (scatter into frag layout)
        #pragma unroll
        for (int l = 0; l < 4; l++) {
            int slot = tid + l*256;             // 1024 float4 slots
            int m = slot >> 3, kg = slot & 7;
            float4 v = *(const float4*)(Wbase + (size_t)m*CI + k0 + kg*4);
            int blk = m >> 4, h8 = (m >> 3) & 1, gr = m & 7;
            int kt = kg >> 1, khalf = kg & 1;
            float* base = sm + APK(buf) + (blk*4 + kt)*128 + gr*16 + khalf*2 + h8;
            base[0]  = f2tf(v.x);
            base[4]  = f2tf(v.y);
            base[8]  = f2tf(v.z);
            base[12] = f2tf(v.w);
        }
        // B: x k-rows k0..k0+31, t-cols t0..t0+127
        #pragma unroll
        for (int l = 0; l < 4; l++) {
            int slot = tid + l*256;             // 1024 float4 slots
            int k = slot >> 5, ng = slot & 31;
            float4 v = *(const float4*)(xb + (size_t)(k0+k)*TL + t0 + ng*4);
            int kt = k >> 3, tgv = k & 3, khalf = (k >> 2) & 1;
            int cc0 = ng*4;
            int wnb = cc0 >> 6, j = (cc0 >> 3) & 7, gb0 = cc0 & 7;
            float* base = sm + BPK(buf) + ((wnb*4 + kt)*8 + j)*64 + gb0*8 + tgv*2 + khalf;
            base[0]  = f2tf(v.x);
            base[8]  = f2tf(v.y);
            base[16] = f2tf(v.z);
            base[24] = f2tf(v.w);
        }
    };

    load_chunk(0, 0);
    __syncthreads();

    for (int c = 0; c < 8; c++) {
        if (c < 7) load_chunk((c+1)*32, (c+1) & 1);
        const float* A_ = sm + APK(c & 1);
        const float* B_ = sm + BPK(c & 1);
        #pragma unroll
        for (int kt = 0; kt < 4; kt++) {
            unsigned a[2][4];
            #pragma unroll
            for (int i = 0; i < 2; i++) {
                float4 f = *(const float4*)(A_ + ((wm*2+i)*4 + kt)*128 + lane*4);
                a[i][0] = __float_as_uint(f.x); a[i][1] = __float_as_uint(f.y);
                a[i][2] = __float_as_uint(f.z); a[i][3] = __float_as_uint(f.w);
            }
            unsigned b[8][2];
            #pragma unroll
            for (int j = 0; j < 8; j++) {
                float2 f = *(const float2*)(B_ + ((wn*4+kt)*8 + j)*64 + lane*2);
                b[j][0] = __float_as_uint(f.x); b[j][1] = __float_as_uint(f.y);
            }
            #pragma unroll
            for (int i = 0; i < 2; i++)
                #pragma unroll
                for (int j = 0; j < 8; j++)
                    mma_tf32(C[i][j], a[i], b[j]);
        }
        __syncthreads();
    }

    // ---- epilogue: stage [t][m] in smem, then coalesced float4 stores ----
    {
        const int g = lane >> 2, tg = lane & 3;
        #pragma unroll
        for (int i = 0; i < 2; i++)
            #pragma unroll
            for (int j = 0; j < 8; j++)
                #pragma unroll
                for (int v = 0; v < 4; v++) {
                    int ml = wm*32 + i*16 + g + ((v >> 1) << 3);
                    int tl = wn*64 + j*8 + tg*2 + (v & 1);
                    sm[tl*132 + ml] = C[i][j][v];
                }
    }
    __syncthreads();

    const float* bias = (m0 < EMB) ? (bq + m0) : (bkv + (m0 - EMB));
    const int kind = (m0 < EMB) ? 0 : (m0 < 2*EMB) ? 1 : 2;
    #pragma unroll
    for (int r = 0; r < 16; r++) {
        int idx = r*256 + tid;
        int t = idx >> 5, m = (idx & 31) * 4;
        float4 v = *(const float4*)(sm + t*132 + m);
        float4 bb = *(const float4*)(bias + m);
        int tgl = t0 + t;
        if (kind == 0) {           // Q: bias + 0.125 scale + tf32 round
            float4 w;
            w.x = f2tf((v.x + bb.x) * 0.125f);
            w.y = f2tf((v.y + bb.y) * 0.125f);
            w.z = f2tf((v.z + bb.z) * 0.125f);
            w.w = f2tf((v.w + bb.w) * 0.125f);
            int o = m0 + m, h = o >> 6, d = o & 63;
            *(float4*)&g_Q[(((size_t)n*NH + h)*TL + tgl)*DH + d] = w;
        } else if (kind == 1) {    // K
            float4 w;
            w.x = f2tf(v.x + bb.x); w.y = f2tf(v.y + bb.y);
            w.z = f2tf(v.z + bb.z); w.w = f2tf(v.w + bb.w);
            int oo = m0 - EMB + m, h = oo >> 6, d = oo & 63;
            *(float4*)&g_K[(((size_t)n*NH + h)*TL + tgl)*DH + d] = w;
        } else {                   // V
            float4 w;
            w.x = f2tf(v.x + bb.x); w.y = f2tf(v.y + bb.y);
            w.z = f2tf(v.z + bb.z); w.w = f2tf(v.w + bb.w);
            int oo = m0 - 2*EMB + m, h = oo >> 5, d = oo & 31;
            *(float4*)&g_V[(((size_t)n*NH + h)*TL + tgl)*DVH + d] = w;
        }
    }
}

// ---------------------------------------------------------------------------
// Causal flash attention: 4 warps x 32 Q-rows, S/P in registers.
// K/V in fragment-packed, double-buffered smem; one barrier per KV tile.
//   Kpack[buf]: 8 ks x 8 nt x 32 lanes x float2 -> 4096 floats/buf
//   Vpack[buf]: 8 kt x 4 nt x 32 lanes x float2 -> 2048 floats/buf
#define KPX(buf) ((buf)*4096)
#define VPX(buf) (8192 + (buf)*2048)
#define ATTN_SMEM_FLOATS 12288
// ---------------------------------------------------------------------------
__global__ __launch_bounds__(128) void attn_mma4()
{
    extern __shared__ float sm[];
    const int qtile = 7 - blockIdx.x;   // heavy tiles first
    const int nh    = blockIdx.y;
    const int tid = threadIdx.x;
    const int wid = tid >> 5, lane = tid & 31;
    const int g = lane >> 2, tg = lane & 3;
    const bool odd = (tg & 1);
    const int sbase = lane & ~3;
    const int s0l = sbase + (tg >> 1);
    const int s1l = s0l + 2;

    const float* Qb = g_Q + ((size_t)nh*TL + qtile*128) * DH;
    const float* Kb = g_K + (size_t)nh*TL*DH;
    const float* Vb = g_V + (size_t)nh*TL*DVH;

    // ---- Q tile 128x64 -> smem (already tf32-rounded & pre-scaled) ----
    #pragma unroll
    for (int l = 0; l < 16; l++) {
        int slot = tid + l*128;
        int s = slot >> 4, dg = slot & 15;
        *(float4*)&sm[s*68 + dg*4] = *(const float4*)(Qb + (size_t)s*DH + dg*4);
    }
    __syncthreads();

    // ---- extract Q fragments ----
    unsigned Aq[2][8][4];
    #pragma unroll
    for (int i = 0; i < 2; i++) {
        const int r = wid*32 + i*16 + g;
        #pragma unroll
        for (int kt = 0; kt < 8; kt++) {
            const int kk = kt*8;
            Aq[i][kt][0] = __float_as_uint(sm[(r  )*68 + kk+tg  ]);
            Aq[i][kt][1] = __float_as_uint(sm[(r+8)*68 + kk+tg  ]);
            Aq[i][kt][2] = __float_as_uint(sm[(r  )*68 + kk+tg+4]);
            Aq[i][kt][3] = __float_as_uint(sm[(r+8)*68 + kk+tg+4]);
        }
    }
    __syncthreads();   // smem reused for K/V buffers

    auto load_kv = [&](int j, int buf) {
        const float* Kt = Kb + (size_t)j*64*DH;
        #pragma unroll
        for (int l = 0; l < 8; l++) {
            int slot = tid + l*128;             // 1024 float4 slots
            int s = slot >> 4, dg = slot & 15;
            float4 v = *(const float4*)(Kt + (size_t)s*DH + dg*4);
            int nt = s >> 3, gg = s & 7;
            int ks = dg >> 1, khalf = dg & 1;
            float* base = sm + KPX(buf) + ((ks*8 + nt)*32 + gg*4)*2 + khalf;
            base[0] = v.x; base[2] = v.y; base[4] = v.z; base[6] = v.w;
        }
        const float* Vt = Vb + (size_t)j*64*DVH;
        #pragma unroll
        for (int l = 0; l < 4; l++) {
            int slot = tid + l*128;             // 512 float4 slots
            int s = slot >> 3, dg = slot & 7;
            float4 v = *(const float4*)(Vt + (size_t)s*DVH + dg*4);
            int kt = s >> 3, tgv = s & 3, khalf = (s >> 2) & 1;
            int nt = dg >> 1, g0 = (dg & 1)*4;
            float* base = sm + VPX(buf) + ((kt*4 + nt)*32 + g0*4 + tgv)*2 + khalf;
            base[0] = v.x; base[8] = v.y; base[16] = v.z; base[24] = v.w;
        }
    };

    float mr[2][2] = {{-1e30f,-1e30f},{-1e30f,-1e30f}};
    float lr[2][2] = {{0,0},{0,0}};
    float O[2][4][4] = {};

    const int jmax = 2*qtile + 1;
    load_kv(0, 0);
    __syncthreads();

    for (int j = 0; j <= jmax; j++) {
        if (j < jmax) load_kv(j+1, (j+1) & 1);
        const float* KP = sm + KPX(j & 1);
        const float* VP = sm + VPX(j & 1);

        // ---- S = Q K^T ----
        float S[2][8][4] = {};
        #pragma unroll
        for (int ks = 0; ks < 8; ks++) {
            unsigned b[8][2];
            #pragma unroll
            for (int nt = 0; nt < 8; nt++) {
                float2 f = *(const float2*)(KP + ((ks*8 + nt)*32 + lane)*2);
                b[nt][0] = __float_as_uint(f.x);
                b[nt][1] = __float_as_uint(f.y);
            }
            #pragma unroll
            for (int i = 0; i < 2; i++)
                #pragma unroll
                for (int nt = 0; nt < 8; nt++)
                    mma_tf32(S[i][nt], Aq[i][ks], b[nt]);
        }

        // ---- causal mask (near diagonal only) ----
        if (j >= 2*qtile) {
            #pragma unroll
            for (int i = 0; i < 2; i++) {
                const int gr0 = qtile*128 + wid*32 + i*16 + g;
                const int gr1 = gr0 + 8;
                #pragma unroll
                for (int nt = 0; nt < 8; nt++) {
                    const int gc = j*64 + nt*8 + tg*2;
                    if (gc   > gr0) S[i][nt][0] = -1e30f;
                    if (gc+1 > gr0) S[i][nt][1] = -1e30f;
                    if (gc   > gr1) S[i][nt][2] = -1e30f;
                    if (gc+1 > gr1) S[i][nt][3] = -1e30f;
                }
            }
        }

        // ---- online softmax ----
        #pragma unroll
        for (int i = 0; i < 2; i++) {
            float mx0 = -1e30f, mx1 = -1e30f;
            #pragma unroll
            for (int nt = 0; nt < 8; nt++) {
                mx0 = fmaxf(mx0, fmaxf(S[i][nt][0], S[i][nt][1]));
                mx1 = fmaxf(mx1, fmaxf(S[i][nt][2], S[i][nt][3]));
            }
            mx0 = fmaxf(mx0, __shfl_xor_sync(0xffffffffu, mx0, 1));
            mx0 = fmaxf(mx0, __shfl_xor_sync(0xffffffffu, mx0, 2));
            mx1 = fmaxf(mx1, __shfl_xor_sync(0xffffffffu, mx1, 1));
            mx1 = fmaxf(mx1, __shfl_xor_sync(0xffffffffu, mx1, 2));
            const float mn0 = fmaxf(mr[i][0], mx0), mn1 = fmaxf(mr[i][1], mx1);
            const float al0 = __expf(mr[i][0] - mn0), al1 = __expf(mr[i][1] - mn1);
            float ps0 = 0.0f, ps1 = 0.0f;
            #pragma unroll
            for (int nt = 0; nt < 8; nt++) {
                S[i][nt][0] = f2tf(__expf(S[i][nt][0] - mn0)); ps0 += S[i][nt][0];
                S[i][nt][1] = f2tf(__expf(S[i][nt][1] - mn0)); ps0 += S[i][nt][1];
                S[i][nt][2] = f2tf(__expf(S[i][nt][2] - mn1)); ps1 += S[i][nt][2];
                S[i][nt][3] = f2tf(__expf(S[i][nt][3] - mn1)); ps1 += S[i][nt][3];
            }
            ps0 += __shfl_xor_sync(0xffffffffu, ps0, 1);
            ps0 += __shfl_xor_sync(0xffffffffu, ps0, 2);
            ps1 += __shfl_xor_sync(0xffffffffu, ps1, 1);
            ps1 += __shfl_xor_sync(0xffffffffu, ps1, 2);
            lr[i][0] = lr[i][0]*al0 + ps0;  mr[i][0] = mn0;
            lr[i][1] = lr[i][1]*al1 + ps1;  mr[i][1] = mn1;
            #pragma unroll
            for (int nt = 0; nt < 4; nt++) {
                O[i][nt][0] *= al0; O[i][nt][1] *= al0;
                O[i][nt][2] *= al1; O[i][nt][3] *= al1;
            }
        }

        // ---- O += P V ----
        #pragma unroll
        for (int kt = 0; kt < 8; kt++) {
            unsigned bv[4][2];
            #pragma unroll
            for (int nt = 0; nt < 4; nt++) {
                float2 f = *(const float2*)(VP + ((kt*4 + nt)*32 + lane)*2);
                bv[nt][0] = __float_as_uint(f.x);
                bv[nt][1] = __float_as_uint(f.y);
            }
            #pragma unroll
            for (int i = 0; i < 2; i++) {
                float x0, x1;
                unsigned a[4];
                x0 = __shfl_sync(0xffffffffu, S[i][kt][0], s0l);
                x1 = __shfl_sync(0xffffffffu, S[i][kt][1], s0l);
                a[0] = __float_as_uint(odd ? x1 : x0);
                x0 = __shfl_sync(0xffffffffu, S[i][kt][2], s0l);
                x1 = __shfl_sync(0xffffffffu, S[i][kt][3], s0l);
                a[1] = __float_as_uint(odd ? x1 : x0);
                x0 = __shfl_sync(0xffffffffu, S[i][kt][0], s1l);
                x1 = __shfl_sync(0xffffffffu, S[i][kt][1], s1l);
                a[2] = __float_as_uint(odd ? x1 : x0);
                x0 = __shfl_sync(0xffffffffu, S[i][kt][2], s1l);
                x1 = __shfl_sync(0xffffffffu, S[i][kt][3], s1l);
                a[3] = __float_as_uint(odd ? x1 : x0);
                #pragma unroll
                for (int nt = 0; nt < 4; nt++)
                    mma_tf32(O[i][nt], a, bv[nt]);
            }
        }
        __syncthreads();   // fence buffers for next iteration
    }

    // ---- normalize + tf32-round + store to g_A (n, c=h*32+d, t) ----
    const int n = nh >> 3, h = nh & 7;
    #pragma unroll
    for (int i = 0; i < 2; i++) {
        const float inv0 = 1.0f / lr[i][0], inv1 = 1.0f / lr[i][1];
        const int t_lo = qtile*128 + wid*32 + i*16 + g;
        const int t_hi = t_lo + 8;
        #pragma unroll
        for (int nt = 0; nt < 4; nt++) {
            int ch = h*DVH + nt*8 + tg*2;
            g_A[((size_t)n*OC + ch  )*TL + t_lo] = f2tf(O[i][nt][0] * inv0);
            g_A[((size_t)n*OC + ch+1)*TL + t_lo] = f2tf(O[i][nt][1] * inv0);
            g_A[((size_t)n*OC + ch  )*TL + t_hi] = f2tf(O[i][nt][2] * inv1);
            g_A[((size_t)n*OC + ch+1)*TL + t_hi] = f2tf(O[i][nt][3] * inv1);
        }
    }
}

// ---------------------------------------------------------------------------
// Output projection: CTA 128x128, warp 32x64, fragment-packed double-buffered.
// ---------------------------------------------------------------------------
__global__ __launch_bounds__(256) void oproj_mma(
    const float* __restrict__ Wo, const float* __restrict__ bo,
    float* __restrict__ out)
{
    extern __shared__ float sm[];
    const int n  = blockIdx.z;
    const int m0 = blockIdx.y * 128;
    const int t0 = blockIdx.x * 128;
    const int tid = threadIdx.x;
    const int wid = tid >> 5, lane = tid & 31;
    const int wm = wid & 3, wn = wid >> 2;
    const float* Ab = g_A + (size_t)n * OC * TL;
    const float* Wbase = Wo + (size_t)m0 * OC;

    float C[2][8][4] = {};

    auto load_chunk = [&](int k0, int buf) {
        #pragma unroll
        for (int l = 0; l < 4; l++) {
            int slot = tid + l*256;
            int m = slot >> 3, kg = slot & 7;
            float4 v = *(const float4*)(Wbase + (size_t)m*OC + k0 + kg*4);
            int blk = m >> 4, h8 = (m >> 3) & 1, gr = m & 7;
            int kt = kg >> 1, khalf = kg & 1;
            float* base = sm + APK(buf) + (blk*4 + kt)*128 + gr*16 + khalf*2 + h8;
            base[0]  = f2tf(v.x);
            base[4]  = f2tf(v.y);
            base[8]  = f2tf(v.z);
            base[12] = f2tf(v.w);
        }
        #pragma unroll
        for (int l = 0; l < 4; l++) {
            int slot = tid + l*256;
            int k = slot >> 5, ng = slot & 31;
            float4 v = *(const float4*)(Ab + (size_t)(k0+k)*TL + t0 + ng*4);  // pre-rounded
            int kt = k >> 3, tgv = k & 3, khalf = (k >> 2) & 1;
            int cc0 = ng*4;
            int wnb = cc0 >> 6, j = (cc0 >> 3) & 7, gb0 = cc0 & 7;
            float* base = sm + BPK(buf) + ((wnb*4 + kt)*8 + j)*64 + gb0*8 + tgv*2 + khalf;
            base[0]  = v.x;
            base[8]  = v.y;
            base[16] = v.z;
            base[24] = v.w;
        }
    };

    load_chunk(0, 0);
    __syncthreads();

    for (int c = 0; c < 8; c++) {
        if (c < 7) load_chunk((c+1)*32, (c+1) & 1);
        const float* A_ = sm + APK(c & 1);
        const float* B_ = sm + BPK(c & 1);
        #pragma unroll
        for (int kt = 0; kt < 4; kt++) {
            unsigned a[2][4];
            #pragma unroll
            for (int i = 0; i < 2; i++) {
                float4 f = *(const float4*)(A_ + ((wm*2+i)*4 + kt)*128 + lane*4);
                a[i][0] = __float_as_uint(f.x); a[i][1] = __float_as_uint(f.y);
                a[i][2] = __float_as_uint(f.z); a[i][3] = __float_as_uint(f.w);
            }
            unsigned b[8][2];
            #pragma unroll
            for (int j = 0; j < 8; j++) {
                float2 f = *(const float2*)(B_ + ((wn*4+kt)*8 + j)*64 + lane*2);
                b[j][0] = __float_as_uint(f.x); b[j][1] = __float_as_uint(f.y);
            }
            #pragma unroll
            for (int i = 0; i < 2; i++)
                #pragma unroll
                for (int j = 0; j < 8; j++)
                    mma_tf32(C[i][j], a[i], b[j]);
        }
        __syncthreads();
    }

    // ---- epilogue: stage [m][t], coalesced float4 stores along t ----
    {
        const int g = lane >> 2, tg = lane & 3;
        #pragma unroll
        for (int i = 0; i < 2; i++)
            #pragma unroll
            for (int j = 0; j < 8; j++)
                #pragma unroll
                for (int v = 0; v < 4; v++) {
                    int ml = wm*32 + i*16 + g + ((v >> 1) << 3);
                    int tl = wn*64 + j*8 + tg*2 + (v & 1);
                    sm[ml*132 + tl] = C[i][j][v];
                }
    }
    __syncthreads();

    #pragma unroll
    for (int r = 0; r < 16; r++) {
        int idx = r*256 + tid;
        int m = idx >> 5, tq = (idx & 31) * 4;
        float4 v = *(const float4*)(sm + m*132 + tq);
        float b = bo[m0 + m];
        v.x += b; v.y += b; v.z += b; v.w += b;
        *(float4*)(out + ((size_t)n*OC + m0 + m)*TL + t0 + tq) = v;
    }
}

// ---------------------------------------------------------------------------
extern "C" void kernel_launch(void* const* d_in, const int* in_sizes, int n_in,
                              void* d_out, int out_size)
{
    const float* x   = (const float*)d_in[0];
    const float* Wq  = (const float*)d_in[1];
    const float* bq  = (const float*)d_in[2];
    const float* Wkv = (const float*)d_in[3];
    const float* bkv = (const float*)d_in[4];
    const float* Wo  = (const float*)d_in[5];
    const float* bo  = (const float*)d_in[6];
    float* out = (float*)d_out;

    const size_t proj_smem = (size_t)PROJ_SMEM_FLOATS * sizeof(float);   // ~66KB
    const size_t attn_smem = (size_t)ATTN_SMEM_FLOATS * sizeof(float);   // 48KB
    cudaFuncSetAttribute(qkv_mma,
                         cudaFuncAttributeMaxDynamicSharedMemorySize, (int)proj_smem);
    cudaFuncSetAttribute(oproj_mma,
                         cudaFuncAttributeMaxDynamicSharedMemorySize, (int)proj_smem);
    cudaFuncSetAttribute(attn_mma4,
                         cudaFuncAttributeMaxDynamicSharedMemorySize, (int)attn_smem);

    // 1) QKV: M=1280 (10 tiles of 128), N=1024 (8 tiles of 128), per batch
    qkv_mma<<<dim3(8, 10, NB), 256, proj_smem>>>(x, Wq, bq, Wkv, bkv);

    // 2) flash attention: 8 Q-tiles of 128 rows, 64 (n,h) pairs
    attn_mma4<<<dim3(8, 64), 128, attn_smem>>>();

    // 3) O proj: M=256 (2 tiles), N=1024 (8 tiles)
    oproj_mma<<<dim3(8, 2, NB), 256, proj_smem>>>(Wo, bo, out);
}

// round 7
// speedup vs baseline: 3.1746x; 3.1746x over previous
#include <cuda_runtime.h>
#include <cuda_fp16.h>

#define NB 8
#define CI 256
#define TL 1024
#define EMB 512
#define OC 256
#define NH 8
#define DH 64
#define DVH 32

// Scratch (device globals) — fp16, producers pre-round (same 11-bit mantissa as tf32)
__device__ __half g_Qh[NB*NH*TL*DH];   // (n,h,t,64), pre-scaled by 0.125
__device__ __half g_Kh[NB*NH*TL*DH];   // (n,h,t,64)
__device__ __half g_Vh[NB*NH*TL*DVH];  // (n,h,t,32)
__device__ __half g_Ah[NB*OC*TL];      // attn out, interleaved: [n][cpair][t][2]

// ---------------------------------------------------------------------------
__device__ __forceinline__ unsigned pack2(float lo, float hi) {
    unsigned u;
    asm("cvt.rn.f16x2.f32 %0, %2, %1;" : "=r"(u) : "f"(lo), "f"(hi));
    return u;   // low 16 = lo, high 16 = hi
}

__device__ __forceinline__ void mma_f16(float c[4], const unsigned a[4], const unsigned b[2]) {
    asm volatile(
        "mma.sync.aligned.m16n8k16.row.col.f32.f16.f16.f32 "
        "{%0,%1,%2,%3}, {%4,%5,%6,%7}, {%8,%9}, {%0,%1,%2,%3};"
        : "+f"(c[0]), "+f"(c[1]), "+f"(c[2]), "+f"(c[3])
        : "r"(a[0]), "r"(a[1]), "r"(a[2]), "r"(a[3]),
          "r"(b[0]), "r"(b[1]));
}

// GEMM smem (in half2 units): As[buf]: [128][20] (16 kpairs + pad) = 2560/buf
//                             Bs[buf]: [16][136] (128 n + pad)     = 2176/buf at 5120
#define AS_OFF(buf) ((buf)*2560)
#define BS_OFF(buf) (5120 + (buf)*2176)
#define PROJ_SMEM_BYTES ((5120 + 2*2176) * 4)        // 37,888 B

// ---------------------------------------------------------------------------
// QKV projection: CTA 128(M) x 128(N), warp tile 32x64, K-chunks of 32, fp16.
// ---------------------------------------------------------------------------
__global__ __launch_bounds__(256) void qkv_mma(
    const float* __restrict__ x,
    const float* __restrict__ Wq,  const float* __restrict__ bq,
    const float* __restrict__ Wkv, const float* __restrict__ bkv)
{
    extern __shared__ __align__(16) unsigned char smraw[];
    unsigned* su = (unsigned*)smraw;        // half2 view (read)
    uint2*   su2 = (uint2*)smraw;
    uint4*   su4 = (uint4*)smraw;
    __half*  shh = (__half*)smraw;          // epilogue staging view

    const int n  = blockIdx.z;
    const int m0 = blockIdx.y * 128;
    const int t0 = blockIdx.x * 128;
    const int tid = threadIdx.x;
    const int wid = tid >> 5, lane = tid & 31;
    const int g = lane >> 2, tg = lane & 3;
    const int wm = wid & 3, wn = wid >> 2;
    const float* xb = x + (size_t)n * CI * TL;
    const float* Wbase = (m0 < EMB) ? (Wq + (size_t)m0*CI) : (Wkv + (size_t)(m0-EMB)*CI);

    float C[2][8][4] = {};

    auto load_chunk = [&](int k0, int buf) {
        // A: 128 m x 32 k floats -> half2[m][kpair]
        #pragma unroll
        for (int l = 0; l < 4; l++) {
            int slot = tid + l*256;                  // 1024 float4 tasks
            int m = slot >> 3, kg = slot & 7;
            float4 v = *(const float4*)(Wbase + (size_t)m*CI + k0 + kg*4);
            uint2 w;
            w.x = pack2(v.x, v.y);
            w.y = pack2(v.z, v.w);
            su2[(AS_OFF(buf) >> 1) + m*10 + kg] = w;  // h2 idx m*20+kg*2
        }
        // B: 32 k x 128 t floats -> half2[kpair][t]  (k-even low)
        #pragma unroll
        for (int l = 0; l < 2; l++) {
            int slot = tid + l*256;                  // 512 tasks
            int kp = slot >> 5, tq = (slot & 31) * 4;
            const float* r0 = xb + (size_t)(k0 + 2*kp    )*TL + t0 + tq;
            const float* r1 = xb + (size_t)(k0 + 2*kp + 1)*TL + t0 + tq;
            float4 a = *(const float4*)r0;
            float4 b = *(const float4*)r1;
            uint4 w;
            w.x = pack2(a.x, b.x); w.y = pack2(a.y, b.y);
            w.z = pack2(a.z, b.z); w.w = pack2(a.w, b.w);
            su4[(BS_OFF(buf) >> 2) + kp*34 + (slot & 31)] = w;  // h2 idx kp*136+tq
        }
    };

    load_chunk(0, 0);
    __syncthreads();

    for (int c = 0; c < 8; c++) {
        if (c < 7) load_chunk((c+1)*32, (c+1) & 1);
        const unsigned* A_ = su + AS_OFF(c & 1);
        const unsigned* B_ = su + BS_OFF(c & 1);
        #pragma unroll
        for (int kc = 0; kc < 2; kc++) {
            const int kb = kc*8 + tg;
            unsigned a[2][4];
            #pragma unroll
            for (int i = 0; i < 2; i++) {
                int r = wm*32 + i*16 + g;
                a[i][0] = A_[(r  )*20 + kb  ];
                a[i][1] = A_[(r+8)*20 + kb  ];
                a[i][2] = A_[(r  )*20 + kb+4];
                a[i][3] = A_[(r+8)*20 + kb+4];
            }
            unsigned b[8][2];
            #pragma unroll
            for (int j = 0; j < 8; j++) {
                int col = wn*64 + j*8 + g;
                b[j][0] = B_[(kb  )*136 + col];
                b[j][1] = B_[(kb+4)*136 + col];
            }
            #pragma unroll
            for (int i = 0; i < 2; i++)
                #pragma unroll
                for (int j = 0; j < 8; j++)
                    mma_f16(C[i][j], a[i], b[j]);
        }
        __syncthreads();
    }

    // ---- epilogue: bias+scale at staging (half), then coalesced vector stores ----
    const float* bias = (m0 < EMB) ? (bq + m0) : (bkv + (m0 - EMB));
    const int kind = (m0 < EMB) ? 0 : (m0 < 2*EMB) ? 1 : 2;
    const float scale = (kind == 0) ? 0.125f : 1.0f;
    {
        float br[2][2];
        #pragma unroll
        for (int i = 0; i < 2; i++) {
            br[i][0] = bias[wm*32 + i*16 + g];
            br[i][1] = bias[wm*32 + i*16 + g + 8];
        }
        #pragma unroll
        for (int i = 0; i < 2; i++)
            #pragma unroll
            for (int j = 0; j < 8; j++)
                #pragma unroll
                for (int v = 0; v < 4; v++) {
                    int ml = wm*32 + i*16 + g + ((v >> 1) << 3);
                    int tl = wn*64 + j*8 + tg*2 + (v & 1);
                    shh[tl*136 + ml] = __float2half_rn((C[i][j][v] + br[i][v>>1]) * scale);
                }
    }
    __syncthreads();

    #pragma unroll
    for (int r = 0; r < 8; r++) {
        int idx = r*256 + tid;
        int t = idx >> 4, mq = (idx & 15) * 8;
        uint4 w = *(const uint4*)&shh[t*136 + mq];
        int tgl = t0 + t;
        if (kind == 0) {
            int o = m0 + mq, h = o >> 6, d = o & 63;
            *(uint4*)&g_Qh[(((size_t)n*NH + h)*TL + tgl)*DH + d] = w;
        } else if (kind == 1) {
            int oo = m0 - EMB + mq, h = oo >> 6, d = oo & 63;
            *(uint4*)&g_Kh[(((size_t)n*NH + h)*TL + tgl)*DH + d] = w;
        } else {
            int oo = m0 - 2*EMB + mq, h = oo >> 5, d = oo & 31;
            *(uint4*)&g_Vh[(((size_t)n*NH + h)*TL + tgl)*DVH + d] = w;
        }
    }
}

// ---------------------------------------------------------------------------
// Attention smem (half2 units): K[buf]: [64][36] = 2304; V[buf]: [32][40] = 1280
// Qs overlays at 0: [128][36] = 4608 (pre-loop only)
#define KP_OFF(buf) ((buf)*2304)
#define VP_OFF(buf) (4608 + (buf)*1280)
#define ATTN_SMEM_BYTES ((4608 + 2*1280) * 4)        // 28,672 B
// ---------------------------------------------------------------------------
__global__ __launch_bounds__(128) void attn_mma5()
{
    extern __shared__ __align__(16) unsigned char smraw[];
    unsigned* su = (unsigned*)smraw;
    uint4*   su4 = (uint4*)smraw;

    const int qtile = 7 - blockIdx.x;
    const int nh    = blockIdx.y;
    const int tid = threadIdx.x;
    const int wid = tid >> 5, lane = tid & 31;
    const int g = lane >> 2, tg = lane & 3;

    const __half* Qb = g_Qh + ((size_t)nh*TL + qtile*128) * DH;
    const __half* Kb = g_Kh + (size_t)nh*TL*DH;
    const __half* Vb = g_Vh + (size_t)nh*TL*DVH;

    // ---- Q tile 128x64 halves -> smem [r][36] h2 ----
    #pragma unroll
    for (int l = 0; l < 8; l++) {
        int slot = tid + l*128;
        int s = slot >> 3, dq = slot & 7;
        su4[9*s + dq] = *(const uint4*)(Qb + (size_t)s*DH + dq*8);
    }
    __syncthreads();

    // ---- extract Q fragments: Aq[i][ks][0..3] ----
    unsigned Aq[2][4][4];
    #pragma unroll
    for (int i = 0; i < 2; i++) {
        const int r = wid*32 + i*16 + g;
        #pragma unroll
        for (int ks = 0; ks < 4; ks++) {
            const int kb = ks*8 + tg;
            Aq[i][ks][0] = su[(r  )*36 + kb  ];
            Aq[i][ks][1] = su[(r+8)*36 + kb  ];
            Aq[i][ks][2] = su[(r  )*36 + kb+4];
            Aq[i][ks][3] = su[(r+8)*36 + kb+4];
        }
    }
    __syncthreads();   // Qs region reused for K/V

    auto load_kv = [&](int j, int buf) {
        const __half* Kt = Kb + (size_t)j*64*DH;
        #pragma unroll
        for (int l = 0; l < 4; l++) {
            int slot = tid + l*128;
            int s = slot >> 3, dq = slot & 7;
            su4[(KP_OFF(buf) >> 2) + 9*s + dq] = *(const uint4*)(Kt + (size_t)s*DH + dq*8);
        }
        // V: pack rows (2sp, 2sp+1) into half2 [sp][d]
        {
            int sp = tid >> 2, dq = tid & 3;
            const __half* Vt = Vb + (size_t)j*64*DVH;
            uint4 w0 = *(const uint4*)(Vt + (size_t)(2*sp  )*DVH + dq*8);
            uint4 w1 = *(const uint4*)(Vt + (size_t)(2*sp+1)*DVH + dq*8);
            uint4 o0, o1;
            o0.x = __byte_perm(w0.x, w1.x, 0x5410);
            o0.y = __byte_perm(w0.x, w1.x, 0x7632);
            o0.z = __byte_perm(w0.y, w1.y, 0x5410);
            o0.w = __byte_perm(w0.y, w1.y, 0x7632);
            o1.x = __byte_perm(w0.z, w1.z, 0x5410);
            o1.y = __byte_perm(w0.z, w1.z, 0x7632);
            o1.z = __byte_perm(w0.w, w1.w, 0x5410);
            o1.w = __byte_perm(w0.w, w1.w, 0x7632);
            su4[(VP_OFF(buf) >> 2) + sp*10 + dq*2    ] = o0;
            su4[(VP_OFF(buf) >> 2) + sp*10 + dq*2 + 1] = o1;
        }
    };

    float mr[2][2] = {{-1e30f,-1e30f},{-1e30f,-1e30f}};
    float lr[2][2] = {{0,0},{0,0}};
    float O[2][4][4] = {};

    const int jmax = 2*qtile + 1;
    load_kv(0, 0);
    __syncthreads();

    for (int j = 0; j <= jmax; j++) {
        if (j < jmax) load_kv(j+1, (j+1) & 1);
        const unsigned* KU = su + KP_OFF(j & 1);
        const unsigned* VU = su + VP_OFF(j & 1);

        // ---- S = Q K^T ----
        float S[2][8][4] = {};
        #pragma unroll
        for (int ks = 0; ks < 4; ks++) {
            const int kb = ks*8 + tg;
            unsigned b[8][2];
            #pragma unroll
            for (int nt = 0; nt < 8; nt++) {
                const int c = nt*8 + g;
                b[nt][0] = KU[c*36 + kb  ];
                b[nt][1] = KU[c*36 + kb+4];
            }
            #pragma unroll
            for (int i = 0; i < 2; i++)
                #pragma unroll
                for (int nt = 0; nt < 8; nt++)
                    mma_f16(S[i][nt], Aq[i][ks], b[nt]);
        }

        // ---- causal mask (near diagonal only) ----
        if (j >= 2*qtile) {
            #pragma unroll
            for (int i = 0; i < 2; i++) {
                const int gr0 = qtile*128 + wid*32 + i*16 + g;
                const int gr1 = gr0 + 8;
                #pragma unroll
                for (int nt = 0; nt < 8; nt++) {
                    const int gc = j*64 + nt*8 + tg*2;
                    if (gc   > gr0) S[i][nt][0] = -1e30f;
                    if (gc+1 > gr0) S[i][nt][1] = -1e30f;
                    if (gc   > gr1) S[i][nt][2] = -1e30f;
                    if (gc+1 > gr1) S[i][nt][3] = -1e30f;
                }
            }
        }

        // ---- online softmax (S stays fp32; rounding happens at pack) ----
        #pragma unroll
        for (int i = 0; i < 2; i++) {
            float mx0 = -1e30f, mx1 = -1e30f;
            #pragma unroll
            for (int nt = 0; nt < 8; nt++) {
                mx0 = fmaxf(mx0, fmaxf(S[i][nt][0], S[i][nt][1]));
                mx1 = fmaxf(mx1, fmaxf(S[i][nt][2], S[i][nt][3]));
            }
            mx0 = fmaxf(mx0, __shfl_xor_sync(0xffffffffu, mx0, 1));
            mx0 = fmaxf(mx0, __shfl_xor_sync(0xffffffffu, mx0, 2));
            mx1 = fmaxf(mx1, __shfl_xor_sync(0xffffffffu, mx1, 1));
            mx1 = fmaxf(mx1, __shfl_xor_sync(0xffffffffu, mx1, 2));
            const float mn0 = fmaxf(mr[i][0], mx0), mn1 = fmaxf(mr[i][1], mx1);
            const float al0 = __expf(mr[i][0] - mn0), al1 = __expf(mr[i][1] - mn1);
            float ps0 = 0.0f, ps1 = 0.0f;
            #pragma unroll
            for (int nt = 0; nt < 8; nt++) {
                S[i][nt][0] = __expf(S[i][nt][0] - mn0); ps0 += S[i][nt][0];
                S[i][nt][1] = __expf(S[i][nt][1] - mn0); ps0 += S[i][nt][1];
                S[i][nt][2] = __expf(S[i][nt][2] - mn1); ps1 += S[i][nt][2];
                S[i][nt][3] = __expf(S[i][nt][3] - mn1); ps1 += S[i][nt][3];
            }
            ps0 += __shfl_xor_sync(0xffffffffu, ps0, 1);
            ps0 += __shfl_xor_sync(0xffffffffu, ps0, 2);
            ps1 += __shfl_xor_sync(0xffffffffu, ps1, 1);
            ps1 += __shfl_xor_sync(0xffffffffu, ps1, 2);
            lr[i][0] = lr[i][0]*al0 + ps0;  mr[i][0] = mn0;
            lr[i][1] = lr[i][1]*al1 + ps1;  mr[i][1] = mn1;
            #pragma unroll
            for (int nt = 0; nt < 4; nt++) {
                O[i][nt][0] *= al0; O[i][nt][1] *= al0;
                O[i][nt][2] *= al1; O[i][nt][3] *= al1;
            }
        }

        // ---- O += P V: P C-frag -> fp16 A-frag is a pure local repack ----
        #pragma unroll
        for (int kt = 0; kt < 4; kt++) {
            unsigned bv[4][2];
            #pragma unroll
            for (int nt = 0; nt < 4; nt++) {
                const int c = nt*8 + g;
                bv[nt][0] = VU[(kt*8 + tg  )*40 + c];
                bv[nt][1] = VU[(kt*8 + tg+4)*40 + c];
            }
            #pragma unroll
            for (int i = 0; i < 2; i++) {
                unsigned a[4];
                a[0] = pack2(S[i][2*kt  ][0], S[i][2*kt  ][1]);
                a[1] = pack2(S[i][2*kt  ][2], S[i][2*kt  ][3]);
                a[2] = pack2(S[i][2*kt+1][0], S[i][2*kt+1][1]);
                a[3] = pack2(S[i][2*kt+1][2], S[i][2*kt+1][3]);
                #pragma unroll
                for (int nt = 0; nt < 4; nt++)
                    mma_f16(O[i][nt], a, bv[nt]);
            }
        }
        __syncthreads();
    }

    // ---- normalize + store to g_Ah interleaved [n][cpair][t][2] ----
    const int n = nh >> 3, h = nh & 7;
    unsigned* gA2 = (unsigned*)g_Ah;
    #pragma unroll
    for (int i = 0; i < 2; i++) {
        const float inv0 = 1.0f / lr[i][0], inv1 = 1.0f / lr[i][1];
        const int t_lo = qtile*128 + wid*32 + i*16 + g;
        const int t_hi = t_lo + 8;
        #pragma unroll
        for (int nt = 0; nt < 4; nt++) {
            int chp = h*16 + nt*4 + tg;      // cpair (ch even low)
            gA2[((size_t)n*128 + chp)*TL + t_lo] = pack2(O[i][nt][0]*inv0, O[i][nt][1]*inv0);
            gA2[((size_t)n*128 + chp)*TL + t_hi] = pack2(O[i][nt][2]*inv1, O[i][nt][3]*inv1);
        }
    }
}

// ---------------------------------------------------------------------------
// Output projection: CTA 128x128, warp 32x64, fp16; fp32 epilogue to d_out.
// ---------------------------------------------------------------------------
__global__ __launch_bounds__(256) void oproj_mma(
    const float* __restrict__ Wo, const float* __restrict__ bo,
    float* __restrict__ out)
{
    extern __shared__ __align__(16) unsigned char smraw[];
    unsigned* su = (unsigned*)smraw;
    uint2*   su2 = (uint2*)smraw;
    uint4*   su4 = (uint4*)smraw;
    float*   smf = (float*)smraw;

    const int n  = blockIdx.z;
    const int m0 = blockIdx.y * 128;
    const int t0 = blockIdx.x * 128;
    const int tid = threadIdx.x;
    const int wid = tid >> 5, lane = tid & 31;
    const int g = lane >> 2, tg = lane & 3;
    const int wm = wid & 3, wn = wid >> 2;
    const unsigned* Ab2 = (const unsigned*)g_Ah + (size_t)n*128*TL;   // [cpair][t] h2
    const float* Wbase = Wo + (size_t)m0 * OC;

    float C[2][8][4] = {};

    auto load_chunk = [&](int k0, int buf) {
        #pragma unroll
        for (int l = 0; l < 4; l++) {
            int slot = tid + l*256;
            int m = slot >> 3, kg = slot & 7;
            float4 v = *(const float4*)(Wbase + (size_t)m*OC + k0 + kg*4);
            uint2 w;
            w.x = pack2(v.x, v.y);
            w.y = pack2(v.z, v.w);
            su2[(AS_OFF(buf) >> 1) + m*10 + kg] = w;
        }
        #pragma unroll
        for (int l = 0; l < 2; l++) {
            int slot = tid + l*256;
            int kp = slot >> 5, tq = (slot & 31) * 4;
            uint4 w = *(const uint4*)&Ab2[(size_t)((k0 >> 1) + kp)*TL + t0 + tq];
            su4[(BS_OFF(buf) >> 2) + kp*34 + (slot & 31)] = w;
        }
    };

    load_chunk(0, 0);
    __syncthreads();

    for (int c = 0; c < 8; c++) {
        if (c < 7) load_chunk((c+1)*32, (c+1) & 1);
        const unsigned* A_ = su + AS_OFF(c & 1);
        const unsigned* B_ = su + BS_OFF(c & 1);
        #pragma unroll
        for (int kc = 0; kc < 2; kc++) {
            const int kb = kc*8 + tg;
            unsigned a[2][4];
            #pragma unroll
            for (int i = 0; i < 2; i++) {
                int r = wm*32 + i*16 + g;
                a[i][0] = A_[(r  )*20 + kb  ];
                a[i][1] = A_[(r+8)*20 + kb  ];
                a[i][2] = A_[(r  )*20 + kb+4];
                a[i][3] = A_[(r+8)*20 + kb+4];
            }
            unsigned b[8][2];
            #pragma unroll
            for (int j = 0; j < 8; j++) {
                int col = wn*64 + j*8 + g;
                b[j][0] = B_[(kb  )*136 + col];
                b[j][1] = B_[(kb+4)*136 + col];
            }
            #pragma unroll
            for (int i = 0; i < 2; i++)
                #pragma unroll
                for (int j = 0; j < 8; j++)
                    mma_f16(C[i][j], a[i], b[j]);
        }
        __syncthreads();
    }

    // ---- epilogue: stage fp32 [m][132], coalesced float4 stores ----
    #pragma unroll
    for (int i = 0; i < 2; i++)
        #pragma unroll
        for (int j = 0; j < 8; j++)
            #pragma unroll
            for (int v = 0; v < 4; v++) {
                int ml = wm*32 + i*16 + g + ((v >> 1) << 3);
                int tl = wn*64 + j*8 + tg*2 + (v & 1);
                smf[ml*132 + tl] = C[i][j][v];
            }
    __syncthreads();

    #pragma unroll
    for (int r = 0; r < 16; r++) {
        int idx = r*256 + tid;
        int m = idx >> 5, tq = (idx & 31) * 4;
        float4 v = *(const float4*)(smf + m*132 + tq);
        float b = bo[m0 + m];
        v.x += b; v.y += b; v.z += b; v.w += b;
        *(float4*)(out + ((size_t)n*OC + m0 + m)*TL + t0 + tq) = v;
    }
}

// ---------------------------------------------------------------------------
extern "C" void kernel_launch(void* const* d_in, const int* in_sizes, int n_in,
                              void* d_out, int out_size)
{
    const float* x   = (const float*)d_in[0];
    const float* Wq  = (const float*)d_in[1];
    const float* bq  = (const float*)d_in[2];
    const float* Wkv = (const float*)d_in[3];
    const float* bkv = (const float*)d_in[4];
    const float* Wo  = (const float*)d_in[5];
    const float* bo  = (const float*)d_in[6];
    float* out = (float*)d_out;

    const int oproj_smem = 128*132*4;                // 67,584 B (staging dominates)
    cudaFuncSetAttribute(oproj_mma,
                         cudaFuncAttributeMaxDynamicSharedMemorySize, oproj_smem);

    // 1) QKV: M=1280 (10 tiles of 128), N=1024 (8 tiles of 128), per batch
    qkv_mma<<<dim3(8, 10, NB), 256, PROJ_SMEM_BYTES>>>(x, Wq, bq, Wkv, bkv);

    // 2) flash attention: 8 Q-tiles of 128 rows, 64 (n,h) pairs
    attn_mma5<<<dim3(8, 64), 128, ATTN_SMEM_BYTES>>>();

    // 3) O proj: M=256 (2 tiles), N=1024 (8 tiles)
    oproj_mma<<<dim3(8, 2, NB), 256, oproj_smem>>>(Wo, bo, out);
}

// round 8
// speedup vs baseline: 3.6232x; 1.1413x over previous
#include <cuda_runtime.h>
#include <cuda_fp16.h>

#define NB 8
#define CI 256
#define TL 1024
#define EMB 512
#define OC 256
#define NH 8
#define DH 64
#define DVH 32

// Scratch (device globals)
__device__ __half g_Wh[(EMB+EMB+OC)*CI];  // Wq ‖ Wkv rows, fp16
__device__ __half g_xh[NB*CI*TL];         // x, fp16
__device__ __half g_Woh[OC*OC];           // Wo, fp16
__device__ __half g_Qh[NB*NH*TL*DH];      // (n,h,t,64), pre-scaled by 0.125
__device__ __half g_Kh[NB*NH*TL*DH];      // (n,h,t,64)
__device__ __half g_Vh[NB*NH*TL*DVH];     // (n,h,t,32)
__device__ __half g_Ah[NB*OC*TL];         // attn out, interleaved [n][cpair][t][2]

// ---------------------------------------------------------------------------
__device__ __forceinline__ unsigned pack2(float lo, float hi) {
    unsigned u;
    asm("cvt.rn.f16x2.f32 %0, %2, %1;" : "=r"(u) : "f"(lo), "f"(hi));
    return u;
}

__device__ __forceinline__ void mma_f16(float c[4], const unsigned a[4], const unsigned b[2]) {
    asm volatile(
        "mma.sync.aligned.m16n8k16.row.col.f32.f16.f16.f32 "
        "{%0,%1,%2,%3}, {%4,%5,%6,%7}, {%8,%9}, {%0,%1,%2,%3};"
        : "+f"(c[0]), "+f"(c[1]), "+f"(c[2]), "+f"(c[3])
        : "r"(a[0]), "r"(a[1]), "r"(a[2]), "r"(a[3]),
          "r"(b[0]), "r"(b[1]));
}

__device__ __forceinline__ void ldsm_x4(unsigned& r0, unsigned& r1, unsigned& r2, unsigned& r3,
                                        unsigned addr) {
    asm volatile("ldmatrix.sync.aligned.m8n8.x4.shared.b16 {%0,%1,%2,%3}, [%4];"
                 : "=r"(r0), "=r"(r1), "=r"(r2), "=r"(r3) : "r"(addr));
}
__device__ __forceinline__ void ldsm_x4_t(unsigned& r0, unsigned& r1, unsigned& r2, unsigned& r3,
                                          unsigned addr) {
    asm volatile("ldmatrix.sync.aligned.m8n8.x4.trans.shared.b16 {%0,%1,%2,%3}, [%4];"
                 : "=r"(r0), "=r"(r1), "=r"(r2), "=r"(r3) : "r"(addr));
}

#define CP16(dst, src) \
    asm volatile("cp.async.cg.shared.global [%0], [%1], 16;" :: "r"(dst), "l"(src))
#define CP_COMMIT() asm volatile("cp.async.commit_group;")
#define CP_WAIT1()  asm volatile("cp.async.wait_group 1;")
#define CP_WAIT0()  asm volatile("cp.async.wait_group 0;")

// ---------------------------------------------------------------------------
// Prologue: fp32 -> fp16 conversion of x, W matrices.
// ---------------------------------------------------------------------------
#define NW_TASK 40960      // (1280*256)/8
#define NX_TASK 262144     // (8*256*1024)/8
#define NO_TASK 8192       // (256*256)/8
__global__ __launch_bounds__(256) void cvt_inputs(
    const float* __restrict__ Wq, const float* __restrict__ Wkv,
    const float* __restrict__ x,  const float* __restrict__ Wo)
{
    int id = blockIdx.x * 256 + threadIdx.x;
    const float* src;
    __half* dst;
    if (id < NW_TASK) {
        int e8 = id * 8;
        src = (e8 < EMB*CI) ? (Wq + e8) : (Wkv + (e8 - EMB*CI));
        dst = g_Wh + e8;
    } else if (id < NW_TASK + NX_TASK) {
        int e8 = (id - NW_TASK) * 8;
        src = x + e8;  dst = g_xh + e8;
    } else if (id < NW_TASK + NX_TASK + NO_TASK) {
        int e8 = (id - NW_TASK - NX_TASK) * 8;
        src = Wo + e8; dst = g_Woh + e8;
    } else return;
    float4 v0 = *(const float4*)src;
    float4 v1 = *(const float4*)(src + 4);
    uint4 w;
    w.x = pack2(v0.x, v0.y); w.y = pack2(v0.z, v0.w);
    w.z = pack2(v1.x, v1.y); w.w = pack2(v1.z, v1.w);
    *(uint4*)dst = w;
}

// ---------------------------------------------------------------------------
// QKV projection: CTA 128(M) x 128(N), warp 32x64, fp16, cp.async + ldmatrix.
// smem per buf: A 128 rows x 80B = 10240; B 32 rows x 272B = 8704. 3 bufs.
// ---------------------------------------------------------------------------
#define PBUF_BYTES 18944
#define PA_BYTES 10240
#define QKV_SMEM (3*PBUF_BYTES)     // 56832
__global__ __launch_bounds__(256) void qkv_mma(
    const float* __restrict__ bq, const float* __restrict__ bkv)
{
    extern __shared__ __align__(16) unsigned char smraw[];
    const unsigned sbase = (unsigned)__cvta_generic_to_shared(smraw);
    __half* shh = (__half*)smraw;

    const int n  = blockIdx.z;
    const int m0 = blockIdx.y * 128;
    const int t0 = blockIdx.x * 128;
    const int tid = threadIdx.x;
    const int wid = tid >> 5, lane = tid & 31;
    const int g = lane >> 2, tg = lane & 3;
    const int wm = wid & 3, wn = wid >> 2;

    const __half* Wsrc = g_Wh + (size_t)m0 * CI;
    const __half* xsrc = g_xh + (size_t)n * CI * TL + t0;

    float C[2][8][4] = {};

    auto load_chunk = [&](int k0, int buf) {
        const unsigned abuf = sbase + buf*PBUF_BYTES;
        const unsigned bbuf = abuf + PA_BYTES;
        #pragma unroll
        for (int l = 0; l < 2; l++) {
            int slot = tid + l*256;               // 512: A 128m x 4 chunks
            int m = slot >> 2, cc = slot & 3;
            CP16(abuf + m*80 + cc*16, Wsrc + (size_t)m*CI + k0 + cc*8);
        }
        #pragma unroll
        for (int l = 0; l < 2; l++) {
            int slot = tid + l*256;               // 512: B 32k x 16 chunks
            int k = slot >> 4, cc = slot & 15;
            CP16(bbuf + k*272 + cc*16, xsrc + (size_t)(k0+k)*TL + cc*8);
        }
        CP_COMMIT();
    };

    load_chunk(0, 0);
    load_chunk(32, 1);

    const int lq  = (lane >> 3) & 1;     // row-block within tile pair
    const int lid8 = lane & 7;
    const int lhi = lane >> 4;           // k-high / n-block select

    for (int c = 0; c < 8; c++) {
        if (c < 7) { CP_WAIT1(); } else { CP_WAIT0(); }
        __syncthreads();
        if (c + 2 < 8) load_chunk((c+2)*32, (c+2) % 3);
        const unsigned abuf = sbase + (c % 3)*PBUF_BYTES;
        const unsigned bbuf = abuf + PA_BYTES;
        #pragma unroll
        for (int kc = 0; kc < 2; kc++) {
            unsigned a[2][4];
            #pragma unroll
            for (int i = 0; i < 2; i++) {
                int row = wm*32 + i*16 + lq*8 + lid8;
                ldsm_x4(a[i][0], a[i][1], a[i][2], a[i][3],
                        abuf + row*80 + kc*32 + lhi*16);
            }
            unsigned b[8][2];
            #pragma unroll
            for (int jj = 0; jj < 4; jj++) {
                int krow = kc*16 + lq*8 + lid8;
                int ncol = wn*64 + (jj*2 + lhi)*8;
                ldsm_x4_t(b[2*jj][0], b[2*jj][1], b[2*jj+1][0], b[2*jj+1][1],
                          bbuf + krow*272 + ncol*2);
            }
            #pragma unroll
            for (int i = 0; i < 2; i++)
                #pragma unroll
                for (int j = 0; j < 8; j++)
                    mma_f16(C[i][j], a[i], b[j]);
        }
    }
    __syncthreads();   // done with bufs; reuse for staging

    // ---- epilogue: bias+scale, stage [t][136] half, coalesced uint4 stores ----
    const float* bias = (m0 < EMB) ? (bq + m0) : (bkv + (m0 - EMB));
    const int kind = (m0 < EMB) ? 0 : (m0 < 2*EMB) ? 1 : 2;
    const float scale = (kind == 0) ? 0.125f : 1.0f;
    {
        float br[2][2];
        #pragma unroll
        for (int i = 0; i < 2; i++) {
            br[i][0] = bias[wm*32 + i*16 + g];
            br[i][1] = bias[wm*32 + i*16 + g + 8];
        }
        #pragma unroll
        for (int i = 0; i < 2; i++)
            #pragma unroll
            for (int j = 0; j < 8; j++)
                #pragma unroll
                for (int v = 0; v < 4; v++) {
                    int ml = wm*32 + i*16 + g + ((v >> 1) << 3);
                    int tl = wn*64 + j*8 + tg*2 + (v & 1);
                    shh[tl*136 + ml] = __float2half_rn((C[i][j][v] + br[i][v>>1]) * scale);
                }
    }
    __syncthreads();

    #pragma unroll
    for (int r = 0; r < 8; r++) {
        int idx = r*256 + tid;
        int t = idx >> 4, mq = (idx & 15) * 8;
        uint4 w = *(const uint4*)&shh[t*136 + mq];
        int tgl = t0 + t;
        if (kind == 0) {
            int o = m0 + mq, h = o >> 6, d = o & 63;
            *(uint4*)&g_Qh[(((size_t)n*NH + h)*TL + tgl)*DH + d] = w;
        } else if (kind == 1) {
            int oo = m0 - EMB + mq, h = oo >> 6, d = oo & 63;
            *(uint4*)&g_Kh[(((size_t)n*NH + h)*TL + tgl)*DH + d] = w;
        } else {
            int oo = m0 - 2*EMB + mq, h = oo >> 5, d = oo & 31;
            *(uint4*)&g_Vh[(((size_t)n*NH + h)*TL + tgl)*DVH + d] = w;
        }
    }
}

// ---------------------------------------------------------------------------
// Attention (unchanged from round 7)
// ---------------------------------------------------------------------------
#define KP_OFF(buf) ((buf)*2304)
#define VP_OFF(buf) (4608 + (buf)*1280)
#define ATTN_SMEM_BYTES ((4608 + 2*1280) * 4)        // 28,672 B
__global__ __launch_bounds__(128) void attn_mma5()
{
    extern __shared__ __align__(16) unsigned char smraw[];
    unsigned* su = (unsigned*)smraw;
    uint4*   su4 = (uint4*)smraw;

    const int qtile = 7 - blockIdx.x;
    const int nh    = blockIdx.y;
    const int tid = threadIdx.x;
    const int wid = tid >> 5, lane = tid & 31;
    const int g = lane >> 2, tg = lane & 3;

    const __half* Qb = g_Qh + ((size_t)nh*TL + qtile*128) * DH;
    const __half* Kb = g_Kh + (size_t)nh*TL*DH;
    const __half* Vb = g_Vh + (size_t)nh*TL*DVH;

    #pragma unroll
    for (int l = 0; l < 8; l++) {
        int slot = tid + l*128;
        int s = slot >> 3, dq = slot & 7;
        su4[9*s + dq] = *(const uint4*)(Qb + (size_t)s*DH + dq*8);
    }
    __syncthreads();

    unsigned Aq[2][4][4];
    #pragma unroll
    for (int i = 0; i < 2; i++) {
        const int r = wid*32 + i*16 + g;
        #pragma unroll
        for (int ks = 0; ks < 4; ks++) {
            const int kb = ks*8 + tg;
            Aq[i][ks][0] = su[(r  )*36 + kb  ];
            Aq[i][ks][1] = su[(r+8)*36 + kb  ];
            Aq[i][ks][2] = su[(r  )*36 + kb+4];
            Aq[i][ks][3] = su[(r+8)*36 + kb+4];
        }
    }
    __syncthreads();

    auto load_kv = [&](int j, int buf) {
        const __half* Kt = Kb + (size_t)j*64*DH;
        #pragma unroll
        for (int l = 0; l < 4; l++) {
            int slot = tid + l*128;
            int s = slot >> 3, dq = slot & 7;
            su4[(KP_OFF(buf) >> 2) + 9*s + dq] = *(const uint4*)(Kt + (size_t)s*DH + dq*8);
        }
        {
            int sp = tid >> 2, dq = tid & 3;
            const __half* Vt = Vb + (size_t)j*64*DVH;
            uint4 w0 = *(const uint4*)(Vt + (size_t)(2*sp  )*DVH + dq*8);
            uint4 w1 = *(const uint4*)(Vt + (size_t)(2*sp+1)*DVH + dq*8);
            uint4 o0, o1;
            o0.x = __byte_perm(w0.x, w1.x, 0x5410);
            o0.y = __byte_perm(w0.x, w1.x, 0x7632);
            o0.z = __byte_perm(w0.y, w1.y, 0x5410);
            o0.w = __byte_perm(w0.y, w1.y, 0x7632);
            o1.x = __byte_perm(w0.z, w1.z, 0x5410);
            o1.y = __byte_perm(w0.z, w1.z, 0x7632);
            o1.z = __byte_perm(w0.w, w1.w, 0x5410);
            o1.w = __byte_perm(w0.w, w1.w, 0x7632);
            su4[(VP_OFF(buf) >> 2) + sp*10 + dq*2    ] = o0;
            su4[(VP_OFF(buf) >> 2) + sp*10 + dq*2 + 1] = o1;
        }
    };

    float mr[2][2] = {{-1e30f,-1e30f},{-1e30f,-1e30f}};
    float lr[2][2] = {{0,0},{0,0}};
    float O[2][4][4] = {};

    const int jmax = 2*qtile + 1;
    load_kv(0, 0);
    __syncthreads();

    for (int j = 0; j <= jmax; j++) {
        if (j < jmax) load_kv(j+1, (j+1) & 1);
        const unsigned* KU = su + KP_OFF(j & 1);
        const unsigned* VU = su + VP_OFF(j & 1);

        float S[2][8][4] = {};
        #pragma unroll
        for (int ks = 0; ks < 4; ks++) {
            const int kb = ks*8 + tg;
            unsigned b[8][2];
            #pragma unroll
            for (int nt = 0; nt < 8; nt++) {
                const int c = nt*8 + g;
                b[nt][0] = KU[c*36 + kb  ];
                b[nt][1] = KU[c*36 + kb+4];
            }
            #pragma unroll
            for (int i = 0; i < 2; i++)
                #pragma unroll
                for (int nt = 0; nt < 8; nt++)
                    mma_f16(S[i][nt], Aq[i][ks], b[nt]);
        }

        if (j >= 2*qtile) {
            #pragma unroll
            for (int i = 0; i < 2; i++) {
                const int gr0 = qtile*128 + wid*32 + i*16 + g;
                const int gr1 = gr0 + 8;
                #pragma unroll
                for (int nt = 0; nt < 8; nt++) {
                    const int gc = j*64 + nt*8 + tg*2;
                    if (gc   > gr0) S[i][nt][0] = -1e30f;
                    if (gc+1 > gr0) S[i][nt][1] = -1e30f;
                    if (gc   > gr1) S[i][nt][2] = -1e30f;
                    if (gc+1 > gr1) S[i][nt][3] = -1e30f;
                }
            }
        }

        #pragma unroll
        for (int i = 0; i < 2; i++) {
            float mx0 = -1e30f, mx1 = -1e30f;
            #pragma unroll
            for (int nt = 0; nt < 8; nt++) {
                mx0 = fmaxf(mx0, fmaxf(S[i][nt][0], S[i][nt][1]));
                mx1 = fmaxf(mx1, fmaxf(S[i][nt][2], S[i][nt][3]));
            }
            mx0 = fmaxf(mx0, __shfl_xor_sync(0xffffffffu, mx0, 1));
            mx0 = fmaxf(mx0, __shfl_xor_sync(0xffffffffu, mx0, 2));
            mx1 = fmaxf(mx1, __shfl_xor_sync(0xffffffffu, mx1, 1));
            mx1 = fmaxf(mx1, __shfl_xor_sync(0xffffffffu, mx1, 2));
            const float mn0 = fmaxf(mr[i][0], mx0), mn1 = fmaxf(mr[i][1], mx1);
            const float al0 = __expf(mr[i][0] - mn0), al1 = __expf(mr[i][1] - mn1);
            float ps0 = 0.0f, ps1 = 0.0f;
            #pragma unroll
            for (int nt = 0; nt < 8; nt++) {
                S[i][nt][0] = __expf(S[i][nt][0] - mn0); ps0 += S[i][nt][0];
                S[i][nt][1] = __expf(S[i][nt][1] - mn0); ps0 += S[i][nt][1];
                S[i][nt][2] = __expf(S[i][nt][2] - mn1); ps1 += S[i][nt][2];
                S[i][nt][3] = __expf(S[i][nt][3] - mn1); ps1 += S[i][nt][3];
            }
            ps0 += __shfl_xor_sync(0xffffffffu, ps0, 1);
            ps0 += __shfl_xor_sync(0xffffffffu, ps0, 2);
            ps1 += __shfl_xor_sync(0xffffffffu, ps1, 1);
            ps1 += __shfl_xor_sync(0xffffffffu, ps1, 2);
            lr[i][0] = lr[i][0]*al0 + ps0;  mr[i][0] = mn0;
            lr[i][1] = lr[i][1]*al1 + ps1;  mr[i][1] = mn1;
            #pragma unroll
            for (int nt = 0; nt < 4; nt++) {
                O[i][nt][0] *= al0; O[i][nt][1] *= al0;
                O[i][nt][2] *= al1; O[i][nt][3] *= al1;
            }
        }

        #pragma unroll
        for (int kt = 0; kt < 4; kt++) {
            unsigned bv[4][2];
            #pragma unroll
            for (int nt = 0; nt < 4; nt++) {
                const int c = nt*8 + g;
                bv[nt][0] = VU[(kt*8 + tg  )*40 + c];
                bv[nt][1] = VU[(kt*8 + tg+4)*40 + c];
            }
            #pragma unroll
            for (int i = 0; i < 2; i++) {
                unsigned a[4];
                a[0] = pack2(S[i][2*kt  ][0], S[i][2*kt  ][1]);
                a[1] = pack2(S[i][2*kt  ][2], S[i][2*kt  ][3]);
                a[2] = pack2(S[i][2*kt+1][0], S[i][2*kt+1][1]);
                a[3] = pack2(S[i][2*kt+1][2], S[i][2*kt+1][3]);
                #pragma unroll
                for (int nt = 0; nt < 4; nt++)
                    mma_f16(O[i][nt], a, bv[nt]);
            }
        }
        __syncthreads();
    }

    const int n = nh >> 3, h = nh & 7;
    unsigned* gA2 = (unsigned*)g_Ah;
    #pragma unroll
    for (int i = 0; i < 2; i++) {
        const float inv0 = 1.0f / lr[i][0], inv1 = 1.0f / lr[i][1];
        const int t_lo = qtile*128 + wid*32 + i*16 + g;
        const int t_hi = t_lo + 8;
        #pragma unroll
        for (int nt = 0; nt < 4; nt++) {
            int chp = h*16 + nt*4 + tg;
            gA2[((size_t)n*128 + chp)*TL + t_lo] = pack2(O[i][nt][0]*inv0, O[i][nt][1]*inv0);
            gA2[((size_t)n*128 + chp)*TL + t_hi] = pack2(O[i][nt][2]*inv1, O[i][nt][3]*inv1);
        }
    }
}

// ---------------------------------------------------------------------------
// Output projection: cp.async + ldmatrix A; B from g_Ah (h2-interleaved).
// smem per buf: A 10240 B + B 16 kp-rows x 544B = 8704 B. 3 bufs + fp32 staging.
// ---------------------------------------------------------------------------
#define OPROJ_SMEM (128*132*4)       // 67584 (staging dominates; > 3*18944)
__global__ __launch_bounds__(256) void oproj_mma(
    const float* __restrict__ bo, float* __restrict__ out)
{
    extern __shared__ __align__(16) unsigned char smraw[];
    const unsigned sbase = (unsigned)__cvta_generic_to_shared(smraw);
    float* smf = (float*)smraw;

    const int n  = blockIdx.z;
    const int m0 = blockIdx.y * 128;
    const int t0 = blockIdx.x * 128;
    const int tid = threadIdx.x;
    const int wid = tid >> 5, lane = tid & 31;
    const int g = lane >> 2, tg = lane & 3;
    const int wm = wid & 3, wn = wid >> 2;

    const __half* Wsrc = g_Woh + (size_t)m0 * OC;
    const __half* Absrc = g_Ah + (size_t)n * 2*128*TL;   // halves, [cpair][t][2]

    float C[2][8][4] = {};

    auto load_chunk = [&](int k0, int buf) {
        const unsigned abuf = sbase + buf*PBUF_BYTES;
        const unsigned bbuf = abuf + PA_BYTES;
        #pragma unroll
        for (int l = 0; l < 2; l++) {
            int slot = tid + l*256;
            int m = slot >> 2, cc = slot & 3;
            CP16(abuf + m*80 + cc*16, Wsrc + (size_t)m*OC + k0 + cc*8);
        }
        #pragma unroll
        for (int l = 0; l < 2; l++) {
            int slot = tid + l*256;               // 512: 16 kp x 32 chunks
            int kp = slot >> 5, cc = slot & 31;
            CP16(bbuf + kp*544 + cc*16,
                 Absrc + ((size_t)((k0 >> 1) + kp)*TL + t0 + cc*4)*2);
        }
        CP_COMMIT();
    };

    load_chunk(0, 0);
    load_chunk(32, 1);

    const int lq = (lane >> 3) & 1;
    const int lid8 = lane & 7;
    const int lhi = lane >> 4;

    for (int c = 0; c < 8; c++) {
        if (c < 7) { CP_WAIT1(); } else { CP_WAIT0(); }
        __syncthreads();
        if (c + 2 < 8) load_chunk((c+2)*32, (c+2) % 3);
        const unsigned abuf = sbase + (c % 3)*PBUF_BYTES;
        const unsigned* B_ = (const unsigned*)(smraw + (c % 3)*PBUF_BYTES + PA_BYTES);
        #pragma unroll
        for (int kc = 0; kc < 2; kc++) {
            unsigned a[2][4];
            #pragma unroll
            for (int i = 0; i < 2; i++) {
                int row = wm*32 + i*16 + lq*8 + lid8;
                ldsm_x4(a[i][0], a[i][1], a[i][2], a[i][3],
                        abuf + row*80 + kc*32 + lhi*16);
            }
            unsigned b[8][2];
            #pragma unroll
            for (int j = 0; j < 8; j++) {
                int col = wn*64 + j*8 + g;
                b[j][0] = B_[(kc*8 + tg  )*136 + col];
                b[j][1] = B_[(kc*8 + tg+4)*136 + col];
            }
            #pragma unroll
            for (int i = 0; i < 2; i++)
                #pragma unroll
                for (int j = 0; j < 8; j++)
                    mma_f16(C[i][j], a[i], b[j]);
        }
    }
    __syncthreads();

    // ---- epilogue: stage fp32 [m][132], coalesced float4 stores ----
    #pragma unroll
    for (int i = 0; i < 2; i++)
        #pragma unroll
        for (int j = 0; j < 8; j++)
            #pragma unroll
            for (int v = 0; v < 4; v++) {
                int ml = wm*32 + i*16 + g + ((v >> 1) << 3);
                int tl = wn*64 + j*8 + tg*2 + (v & 1);
                smf[ml*132 + tl] = C[i][j][v];
            }
    __syncthreads();

    #pragma unroll
    for (int r = 0; r < 16; r++) {
        int idx = r*256 + tid;
        int m = idx >> 5, tq = (idx & 31) * 4;
        float4 v = *(const float4*)(smf + m*132 + tq);
        float b = bo[m0 + m];
        v.x += b; v.y += b; v.z += b; v.w += b;
        *(float4*)(out + ((size_t)n*OC + m0 + m)*TL + t0 + tq) = v;
    }
}

// ---------------------------------------------------------------------------
extern "C" void kernel_launch(void* const* d_in, const int* in_sizes, int n_in,
                              void* d_out, int out_size)
{
    const float* x   = (const float*)d_in[0];
    const float* Wq  = (const float*)d_in[1];
    const float* bq  = (const float*)d_in[2];
    const float* Wkv = (const float*)d_in[3];
    const float* bkv = (const float*)d_in[4];
    const float* Wo  = (const float*)d_in[5];
    const float* bo  = (const float*)d_in[6];
    float* out = (float*)d_out;

    cudaFuncSetAttribute(qkv_mma,
                         cudaFuncAttributeMaxDynamicSharedMemorySize, QKV_SMEM);
    cudaFuncSetAttribute(oproj_mma,
                         cudaFuncAttributeMaxDynamicSharedMemorySize, OPROJ_SMEM);

    // 0) fp32 -> fp16 conversion
    cvt_inputs<<<1216, 256>>>(Wq, Wkv, x, Wo);

    // 1) QKV: M=1280 (10 tiles of 128), N=1024 (8 tiles of 128), per batch
    qkv_mma<<<dim3(8, 10, NB), 256, QKV_SMEM>>>(bq, bkv);

    // 2) flash attention: 8 Q-tiles of 128 rows, 64 (n,h) pairs
    attn_mma5<<<dim3(8, 64), 128, ATTN_SMEM_BYTES>>>();

    // 3) O proj: M=256 (2 tiles), N=1024 (8 tiles)
    oproj_mma<<<dim3(8, 2, NB), 256, OPROJ_SMEM>>>(bo, out);
}